// round 1
// baseline (speedup 1.0000x reference)
#include <cuda_runtime.h>
#include <cstdint>

// Problem constants (fixed by the reference config)
#define SEQ   512
#define BATCH 64
#define NN    1024
#define SIN   64
#define NT    512          // threads per block (2 neurons / thread as float2)
#define NWARP (NT/32)

// Transposed weights: W1T[i][n] = W1[n][i]  (row i = weight row delivered per spike id)
__device__ float g_W1T[NN * NN];
__device__ float g_W2T[NN * NN];

// ---------------------------------------------------------------------------
// Tiled transpose of a 1024x1024 fp32 matrix into one of the device globals.
// which == 0 -> g_W1T, which == 1 -> g_W2T
// ---------------------------------------------------------------------------
__global__ void transpose1024(const float* __restrict__ in, int which) {
    __shared__ float tile[32][33];
    float* out = which ? g_W2T : g_W1T;
    int bx = blockIdx.x * 32, by = blockIdx.y * 32;
    int tx = threadIdx.x, ty = threadIdx.y;
#pragma unroll
    for (int j = 0; j < 32; j += 8)
        tile[ty + j][tx] = in[(size_t)(by + ty + j) * NN + (bx + tx)];
    __syncthreads();
#pragma unroll
    for (int j = 0; j < 32; j += 8)
        out[(size_t)(bx + ty + j) * NN + (by + tx)] = tile[tx][ty + j];
}

// ---------------------------------------------------------------------------
// Persistent LIF kernel: one CTA per batch element, loops over all SEQ steps.
// Thread t owns neurons {2t, 2t+1} of BOTH layers (float2 state in registers).
// ---------------------------------------------------------------------------
__global__ __launch_bounds__(NT, 1)
void lif_persistent(const float* __restrict__ decay1, const float* __restrict__ decay2,
                    const float* __restrict__ th1,    const float* __restrict__ th2,
                    const float* __restrict__ v1init, const float* __restrict__ v2init,
                    const int*   __restrict__ spk_ids, const int* __restrict__ spk_num,
                    float* __restrict__ out)
{
    const int b    = blockIdx.x;
    const int tid  = threadIdx.x;
    const int lane = tid & 31;
    const int warp = tid >> 5;

    // Output sections, element offsets (reference tuple order, all as fp32)
    float* out_ids1 = out;
    float* out_ids2 = out + (size_t)SEQ * BATCH * SIN;
    float* out_cnt1 = out + (size_t)2 * SEQ * BATCH * SIN;
    float* out_cnt2 = out_cnt1 + (size_t)SEQ * BATCH * 2;
    float* out_st1  = out_cnt2 + (size_t)SEQ * BATCH * 2;
    float* out_st2  = out_st1  + (size_t)SEQ * BATCH * NN;

    // Per-thread state and parameters
    float2 v1 = ((const float2*)v1init)[b * (NN / 2) + tid];
    float2 v2 = ((const float2*)v2init)[b * (NN / 2) + tid];
    const float2 d1 = ((const float2*)decay1)[tid];
    const float2 d2 = ((const float2*)decay2)[tid];
    const float2 t1 = ((const float2*)th1)[tid];
    const float2 t2 = ((const float2*)th2)[tid];
    const float od1x = 1.0f - d1.x, od1y = 1.0f - d1.y;
    const float od2x = 1.0f - d2.x, od2y = 1.0f - d2.y;
    const float h1x = 0.9f * t1.x,  h1y = 0.9f * t1.y;   // SECOND_TH_FRAC * th
    const float h2x = 0.9f * t2.x,  h2y = 0.9f * t2.y;

    __shared__ int s_ids[SIN];
    __shared__ int s_num;
    __shared__ int s_spk[NN];     // layer-1 spiking neuron ids (ascending), full list
    __shared__ int s_ns[SIN];     // layer-1 non-spiking padding ids (first 64)
    __shared__ int s_spk2[SIN];   // layer-2 spiking ids (first 64 only needed)
    __shared__ int s_ns2[SIN];
    __shared__ int s_wsum[NWARP];
    __shared__ int s_tot;

    const float2* __restrict__ W1 = (const float2*)g_W1T;
    const float2* __restrict__ W2 = (const float2*)g_W2T;

    for (int t = 0; t < SEQ; t++) {
        // ---- stage input spikes for this (t, b) ----
        if (tid < SIN) s_ids[tid] = spk_ids[((size_t)t * BATCH + b) * SIN + tid];
        if (tid == 0)  s_num = spk_num[t * BATCH + b];
        __syncthreads();

        // ---- layer 1: sparse gather-accumulate of W1T rows ----
        const int num = s_num;
        float2 acc = make_float2(0.0f, 0.0f);
#pragma unroll 8
        for (int s = 0; s < num; s++) {
            float2 w = W1[s_ids[s] * (NN / 2) + tid];
            acc.x += w.x; acc.y += w.y;
        }

        v1.x = d1.x * v1.x + od1x * acc.x;
        v1.y = d1.y * v1.y + od1y * acc.y;
        const bool p0 = v1.x > t1.x;
        const bool p1 = v1.y > t1.y;
        int c  = (int)p0 + (int)p1;
        int c2 = (int)(v1.x > h1x) + (int)(v1.y > h1y);

        // ---- packed prefix sum: low 16 bits = spike count, high = second count ----
        int packed = c | (c2 << 16);
        int incl = packed;
#pragma unroll
        for (int o = 1; o < 32; o <<= 1) {
            int y = __shfl_up_sync(0xffffffffu, incl, o);
            if (lane >= o) incl += y;
        }
        if (lane == 31) s_wsum[warp] = incl;
        __syncthreads();
        if (tid == 0) {
            int a = 0;
#pragma unroll
            for (int w = 0; w < NWARP; w++) { int v = s_wsum[w]; s_wsum[w] = a; a += v; }
            s_tot = a;
        }
        __syncthreads();
        const int exBase  = s_wsum[warp] + (incl - packed);
        int gp            = exBase & 0xffff;            // exclusive spike prefix
        const int tot     = s_tot;
        const int c1tot   = tot & 0xffff;
        const int c2tot   = tot >> 16;

        // ---- emit compacted spike / padding lists, reset, write state trace ----
        const int n0 = tid * 2;
        if (p0) { s_spk[gp++] = n0; }
        else    { int np = n0 - gp; if (np < SIN) s_ns[np] = n0; }
        if (p1) { s_spk[gp++] = n0 + 1; }
        else    { int np = (n0 + 1) - gp; if (np < SIN) s_ns[np] = n0 + 1; }
        if (p0) v1.x = 0.0f;
        if (p1) v1.y = 0.0f;
        ((float2*)(out_st1 + ((size_t)t * BATCH + b) * NN))[tid] = v1;
        __syncthreads();

        if (tid < SIN) {
            int id = (tid < c1tot) ? s_spk[tid] : s_ns[tid - c1tot];
            out_ids1[((size_t)t * BATCH + b) * SIN + tid] = (float)id;
        }
        if (tid < 2)
            out_cnt1[((size_t)t * BATCH + b) * 2 + tid] = (float)(tid == 0 ? c1tot : c2tot);

        // ---- layer 2: gather W2T rows of spiking layer-1 neurons ----
        float2 acc2 = make_float2(0.0f, 0.0f);
#pragma unroll 8
        for (int s = 0; s < c1tot; s++) {
            float2 w = W2[s_spk[s] * (NN / 2) + tid];
            acc2.x += w.x; acc2.y += w.y;
        }

        v2.x = d2.x * v2.x + od2x * acc2.x;
        v2.y = d2.y * v2.y + od2y * acc2.y;
        const bool q0 = v2.x > t2.x;
        const bool q1 = v2.y > t2.y;
        c  = (int)q0 + (int)q1;
        c2 = (int)(v2.x > h2x) + (int)(v2.y > h2y);

        packed = c | (c2 << 16);
        incl = packed;
#pragma unroll
        for (int o = 1; o < 32; o <<= 1) {
            int y = __shfl_up_sync(0xffffffffu, incl, o);
            if (lane >= o) incl += y;
        }
        if (lane == 31) s_wsum[warp] = incl;
        __syncthreads();
        if (tid == 0) {
            int a = 0;
#pragma unroll
            for (int w = 0; w < NWARP; w++) { int v = s_wsum[w]; s_wsum[w] = a; a += v; }
            s_tot = a;
        }
        __syncthreads();
        const int exBase2 = s_wsum[warp] + (incl - packed);
        int gq            = exBase2 & 0xffff;
        const int tot2    = s_tot;
        const int c1tot2  = tot2 & 0xffff;
        const int c2tot2  = tot2 >> 16;

        if (q0) { if (gq < SIN) s_spk2[gq] = n0;     gq++; }
        else    { int np = n0 - gq;       if (np < SIN) s_ns2[np] = n0; }
        if (q1) { if (gq < SIN) s_spk2[gq] = n0 + 1; gq++; }
        else    { int np = (n0 + 1) - gq; if (np < SIN) s_ns2[np] = n0 + 1; }
        if (q0) v2.x = 0.0f;
        if (q1) v2.y = 0.0f;
        ((float2*)(out_st2 + ((size_t)t * BATCH + b) * NN))[tid] = v2;
        __syncthreads();

        if (tid < SIN) {
            int id = (tid < c1tot2) ? s_spk2[tid] : s_ns2[tid - c1tot2];
            out_ids2[((size_t)t * BATCH + b) * SIN + tid] = (float)id;
        }
        if (tid < 2)
            out_cnt2[((size_t)t * BATCH + b) * 2 + tid] = (float)(tid == 0 ? c1tot2 : c2tot2);
        // Reuse of s_ids / s_spk next iteration is protected by the sync at the
        // top of the next iteration plus the scan syncs in between.
    }
}

// ---------------------------------------------------------------------------
// Inputs (metadata order): W1, W2, decay1, decay2, th1, th2,
//                          init_state_0, init_state_1, inp_spike_ids, num_inp_spikes
// Output: concat(ids1, ids2, cnt1, cnt2, st1, st2) as fp32
// ---------------------------------------------------------------------------
extern "C" void kernel_launch(void* const* d_in, const int* in_sizes, int n_in,
                              void* d_out, int out_size) {
    const float* W1     = (const float*)d_in[0];
    const float* W2     = (const float*)d_in[1];
    const float* decay1 = (const float*)d_in[2];
    const float* decay2 = (const float*)d_in[3];
    const float* th1    = (const float*)d_in[4];
    const float* th2    = (const float*)d_in[5];
    const float* v1init = (const float*)d_in[6];
    const float* v2init = (const float*)d_in[7];
    const int*   spkids = (const int*)d_in[8];
    const int*   spknum = (const int*)d_in[9];
    float* out = (float*)d_out;

    dim3 tb(32, 8), tg(32, 32);
    transpose1024<<<tg, tb>>>(W1, 0);
    transpose1024<<<tg, tb>>>(W2, 1);
    lif_persistent<<<BATCH, NT>>>(decay1, decay2, th1, th2,
                                  v1init, v2init, spkids, spknum, out);
}

// round 2
// speedup vs baseline: 1.1225x; 1.1225x over previous
#include <cuda_runtime.h>
#include <cstdint>

// Problem constants (fixed by the reference config)
#define SEQ   512
#define BATCH 64
#define NN    1024
#define SIN   64
#define NT    512          // threads per block (2 neurons / thread as float2)
#define NWARP (NT/32)

// Transposed weights: W1T[i][n] = W1[n][i]
__device__ float g_W1T[NN * NN];
__device__ float g_W2T[NN * NN];

// ---------------------------------------------------------------------------
// Tiled transpose of a 1024x1024 fp32 matrix into one of the device globals.
// ---------------------------------------------------------------------------
__global__ void transpose1024(const float* __restrict__ in, int which) {
    __shared__ float tile[32][33];
    float* out = which ? g_W2T : g_W1T;
    int bx = blockIdx.x * 32, by = blockIdx.y * 32;
    int tx = threadIdx.x, ty = threadIdx.y;
#pragma unroll
    for (int j = 0; j < 32; j += 8)
        tile[ty + j][tx] = in[(size_t)(by + ty + j) * NN + (bx + tx)];
    __syncthreads();
#pragma unroll
    for (int j = 0; j < 32; j += 8)
        out[(size_t)(bx + ty + j) * NN + (by + tx)] = tile[tx][ty + j];
}

// ---------------------------------------------------------------------------
// Deep-MLP gather: accumulate rows W[off[s] + tid] for s in [0, num).
// Issues loads in chunks of 32 independent predicated LDG.64 before any FADD,
// so the L2 round-trip (~250cyc) is paid ~once per 32 rows instead of per 8.
// off[] holds pre-scaled row offsets (id * NN/2). num is CTA-uniform.
// ---------------------------------------------------------------------------
__device__ __forceinline__ float2 gather_rows(const float2* __restrict__ W,
                                              const int* __restrict__ off,
                                              int num, int tid)
{
    float2 acc = make_float2(0.0f, 0.0f);
#pragma unroll
    for (int c = 0; c < SIN; c += 32) {
        if (c < num) {                      // uniform branch
            float2 w[32];
#pragma unroll
            for (int j = 0; j < 32; j++) {
                int s = c + j;
                if (s < num) w[j] = W[off[s] + tid];   // uniform predicate
                else         w[j] = make_float2(0.0f, 0.0f);
            }
            // pairwise tree to shorten the FADD dependency chain
            float2 p0 = make_float2(0.f,0.f), p1 = make_float2(0.f,0.f),
                   p2 = make_float2(0.f,0.f), p3 = make_float2(0.f,0.f);
#pragma unroll
            for (int j = 0; j < 32; j += 4) {
                p0.x += w[j+0].x; p0.y += w[j+0].y;
                p1.x += w[j+1].x; p1.y += w[j+1].y;
                p2.x += w[j+2].x; p2.y += w[j+2].y;
                p3.x += w[j+3].x; p3.y += w[j+3].y;
            }
            acc.x += (p0.x + p1.x) + (p2.x + p3.x);
            acc.y += (p0.y + p1.y) + (p2.y + p3.y);
        }
    }
    return acc;
}

// ---------------------------------------------------------------------------
// Persistent LIF kernel: one CTA per batch element, loops over all SEQ steps.
// Thread t owns neurons {2t, 2t+1} of BOTH layers (float2 state in registers).
// ---------------------------------------------------------------------------
__global__ __launch_bounds__(NT, 1)
void lif_persistent(const float* __restrict__ decay1, const float* __restrict__ decay2,
                    const float* __restrict__ th1,    const float* __restrict__ th2,
                    const float* __restrict__ v1init, const float* __restrict__ v2init,
                    const int*   __restrict__ spk_ids, const int* __restrict__ spk_num,
                    float* __restrict__ out)
{
    const int b    = blockIdx.x;
    const int tid  = threadIdx.x;
    const int lane = tid & 31;
    const int warp = tid >> 5;

    // Output sections (reference tuple order, all fp32)
    float* out_ids1 = out;
    float* out_ids2 = out + (size_t)SEQ * BATCH * SIN;
    float* out_cnt1 = out + (size_t)2 * SEQ * BATCH * SIN;
    float* out_cnt2 = out_cnt1 + (size_t)SEQ * BATCH * 2;
    float* out_st1  = out_cnt2 + (size_t)SEQ * BATCH * 2;
    float* out_st2  = out_st1  + (size_t)SEQ * BATCH * NN;

    float2 v1 = ((const float2*)v1init)[b * (NN / 2) + tid];
    float2 v2 = ((const float2*)v2init)[b * (NN / 2) + tid];
    const float2 d1 = ((const float2*)decay1)[tid];
    const float2 d2 = ((const float2*)decay2)[tid];
    const float2 t1 = ((const float2*)th1)[tid];
    const float2 t2 = ((const float2*)th2)[tid];
    const float od1x = 1.0f - d1.x, od1y = 1.0f - d1.y;
    const float od2x = 1.0f - d2.x, od2y = 1.0f - d2.y;
    const float h1x = 0.9f * t1.x,  h1y = 0.9f * t1.y;
    const float h2x = 0.9f * t2.x,  h2y = 0.9f * t2.y;

    __shared__ int s_ids[SIN];     // pre-scaled row offsets (id * NN/2)
    __shared__ int s_num;
    __shared__ int s_spk[NN];      // layer-1 spiking ids (ascending)
    __shared__ int s_spkoff[NN];   // same, pre-scaled for W2 gather
    __shared__ int s_ns[SIN];      // layer-1 non-spiking padding ids
    __shared__ int s_spk2[SIN];
    __shared__ int s_ns2[SIN];
    __shared__ int s_wsum[NWARP];
    __shared__ int s_tot;

    const float2* __restrict__ W1 = (const float2*)g_W1T;
    const float2* __restrict__ W2 = (const float2*)g_W2T;

    for (int t = 0; t < SEQ; t++) {
        // ---- stage input spikes ----
        if (tid < SIN) s_ids[tid] = spk_ids[((size_t)t * BATCH + b) * SIN + tid] * (NN / 2);
        if (tid == 0)  s_num = spk_num[t * BATCH + b];
        __syncthreads();

        // ---- layer 1: sparse gather-accumulate ----
        const int num = s_num;
        float2 acc = gather_rows(W1, s_ids, num, tid);

        v1.x = d1.x * v1.x + od1x * acc.x;
        v1.y = d1.y * v1.y + od1y * acc.y;
        const bool p0 = v1.x > t1.x;
        const bool p1 = v1.y > t1.y;
        int c  = (int)p0 + (int)p1;
        int c2 = (int)(v1.x > h1x) + (int)(v1.y > h1y);

        // ---- packed scan: low16 = spike count, high16 = second count ----
        int packed = c | (c2 << 16);
        int incl = packed;
#pragma unroll
        for (int o = 1; o < 32; o <<= 1) {
            int y = __shfl_up_sync(0xffffffffu, incl, o);
            if (lane >= o) incl += y;
        }
        if (lane == 31) s_wsum[warp] = incl;
        __syncthreads();
        if (warp == 0) {                       // warp-parallel 16-elem scan
            int v = (lane < NWARP) ? s_wsum[lane] : 0;
            int e = v;
#pragma unroll
            for (int o = 1; o < 16; o <<= 1) {
                int y = __shfl_up_sync(0xffffffffu, e, o);
                if (lane >= o) e += y;
            }
            if (lane < NWARP) s_wsum[lane] = e - v;   // exclusive
            if (lane == NWARP - 1) s_tot = e;
        }
        __syncthreads();
        const int exBase  = s_wsum[warp] + (incl - packed);
        int gp            = exBase & 0xffff;
        const int tot     = s_tot;
        const int c1tot   = tot & 0xffff;
        const int c2tot   = tot >> 16;

        // ---- emit compacted lists, reset, write state trace ----
        const int n0 = tid * 2;
        if (p0) { s_spk[gp] = n0;     s_spkoff[gp] = n0 * (NN / 2);       gp++; }
        else    { int np = n0 - gp;       if (np < SIN) s_ns[np] = n0; }
        if (p1) { s_spk[gp] = n0 + 1; s_spkoff[gp] = (n0 + 1) * (NN / 2); gp++; }
        else    { int np = (n0 + 1) - gp; if (np < SIN) s_ns[np] = n0 + 1; }
        if (p0) v1.x = 0.0f;
        if (p1) v1.y = 0.0f;
        __stcs(&((float2*)(out_st1 + ((size_t)t * BATCH + b) * NN))[tid], v1);
        __syncthreads();

        if (tid < SIN) {
            int id = (tid < c1tot) ? s_spk[tid] : s_ns[tid - c1tot];
            out_ids1[((size_t)t * BATCH + b) * SIN + tid] = (float)id;
        }
        if (tid < 2)
            out_cnt1[((size_t)t * BATCH + b) * 2 + tid] = (float)(tid == 0 ? c1tot : c2tot);

        // ---- layer 2 ----
        float2 acc2 = make_float2(0.0f, 0.0f);
        if (c1tot <= SIN) {
            acc2 = gather_rows(W2, s_spkoff, c1tot, tid);
        } else {
            for (int s = 0; s < c1tot; s += 32) {
                float2 w[32];
#pragma unroll
                for (int j = 0; j < 32; j++) {
                    int ss = s + j;
                    if (ss < c1tot) w[j] = W2[s_spkoff[ss] + tid];
                    else            w[j] = make_float2(0.0f, 0.0f);
                }
#pragma unroll
                for (int j = 0; j < 32; j++) { acc2.x += w[j].x; acc2.y += w[j].y; }
            }
        }

        v2.x = d2.x * v2.x + od2x * acc2.x;
        v2.y = d2.y * v2.y + od2y * acc2.y;
        const bool q0 = v2.x > t2.x;
        const bool q1 = v2.y > t2.y;
        c  = (int)q0 + (int)q1;
        c2 = (int)(v2.x > h2x) + (int)(v2.y > h2y);

        packed = c | (c2 << 16);
        incl = packed;
#pragma unroll
        for (int o = 1; o < 32; o <<= 1) {
            int y = __shfl_up_sync(0xffffffffu, incl, o);
            if (lane >= o) incl += y;
        }
        if (lane == 31) s_wsum[warp] = incl;
        __syncthreads();
        if (warp == 0) {
            int v = (lane < NWARP) ? s_wsum[lane] : 0;
            int e = v;
#pragma unroll
            for (int o = 1; o < 16; o <<= 1) {
                int y = __shfl_up_sync(0xffffffffu, e, o);
                if (lane >= o) e += y;
            }
            if (lane < NWARP) s_wsum[lane] = e - v;
            if (lane == NWARP - 1) s_tot = e;
        }
        __syncthreads();
        const int exBase2 = s_wsum[warp] + (incl - packed);
        int gq            = exBase2 & 0xffff;
        const int tot2    = s_tot;
        const int c1tot2  = tot2 & 0xffff;
        const int c2tot2  = tot2 >> 16;

        if (q0) { if (gq < SIN) s_spk2[gq] = n0;     gq++; }
        else    { int np = n0 - gq;       if (np < SIN) s_ns2[np] = n0; }
        if (q1) { if (gq < SIN) s_spk2[gq] = n0 + 1; gq++; }
        else    { int np = (n0 + 1) - gq; if (np < SIN) s_ns2[np] = n0 + 1; }
        if (q0) v2.x = 0.0f;
        if (q1) v2.y = 0.0f;
        __stcs(&((float2*)(out_st2 + ((size_t)t * BATCH + b) * NN))[tid], v2);
        __syncthreads();

        if (tid < SIN) {
            int id = (tid < c1tot2) ? s_spk2[tid] : s_ns2[tid - c1tot2];
            out_ids2[((size_t)t * BATCH + b) * SIN + tid] = (float)id;
        }
        if (tid < 2)
            out_cnt2[((size_t)t * BATCH + b) * 2 + tid] = (float)(tid == 0 ? c1tot2 : c2tot2);
    }
}

// ---------------------------------------------------------------------------
extern "C" void kernel_launch(void* const* d_in, const int* in_sizes, int n_in,
                              void* d_out, int out_size) {
    const float* W1     = (const float*)d_in[0];
    const float* W2     = (const float*)d_in[1];
    const float* decay1 = (const float*)d_in[2];
    const float* decay2 = (const float*)d_in[3];
    const float* th1    = (const float*)d_in[4];
    const float* th2    = (const float*)d_in[5];
    const float* v1init = (const float*)d_in[6];
    const float* v2init = (const float*)d_in[7];
    const int*   spkids = (const int*)d_in[8];
    const int*   spknum = (const int*)d_in[9];
    float* out = (float*)d_out;

    dim3 tb(32, 8), tg(32, 32);
    transpose1024<<<tg, tb>>>(W1, 0);
    transpose1024<<<tg, tb>>>(W2, 1);
    lif_persistent<<<BATCH, NT>>>(decay1, decay2, th1, th2,
                                  v1init, v2init, spkids, spknum, out);
}

// round 7
// speedup vs baseline: 1.2365x; 1.1016x over previous
#include <cuda_runtime.h>
#include <cstdint>

// Problem constants (fixed by the reference config)
#define SEQ   512
#define BATCH 64
#define NN    1024
#define SIN   64
#define NT    256          // threads per block (4 neurons / thread as float4)
#define NWARP (NT/32)      // 8
#define ROWF4 (NN/4)       // 256 float4 per weight row

// Transposed weights: W1T[i][n] = W1[n][i]
__device__ float g_W1T[NN * NN];
__device__ float g_W2T[NN * NN];

// ---------------------------------------------------------------------------
// Tiled transpose of both 1024x1024 fp32 matrices (blockIdx.z selects matrix).
// ---------------------------------------------------------------------------
__global__ void transpose_both(const float* __restrict__ W1in,
                               const float* __restrict__ W2in) {
    __shared__ float tile[32][33];
    const float* in  = blockIdx.z ? W2in : W1in;
    float*       out = blockIdx.z ? g_W2T : g_W1T;
    int bx = blockIdx.x * 32, by = blockIdx.y * 32;
    int tx = threadIdx.x, ty = threadIdx.y;
#pragma unroll
    for (int j = 0; j < 32; j += 8)
        tile[ty + j][tx] = in[(size_t)(by + ty + j) * NN + (bx + tx)];
    __syncthreads();
#pragma unroll
    for (int j = 0; j < 32; j += 8)
        out[(size_t)(bx + ty + j) * NN + (by + tx)] = tile[tx][ty + j];
}

// ---------------------------------------------------------------------------
// Gather-accumulate rows W4[off[s] + tid] for s in [0, num).
// Chunks of 16 independent LDG.128 (64-reg buffer) before any FADD: one L2
// round-trip amortized over 16 rows. off[] pre-scaled to float4 row offsets.
// num is CTA-uniform, so all branches are uniform.
// ---------------------------------------------------------------------------
__device__ __forceinline__ float4 gather_rows4(const float4* __restrict__ W4,
                                               const int* __restrict__ off,
                                               int num, int tid)
{
    float4 acc = make_float4(0.f, 0.f, 0.f, 0.f);
    for (int c = 0; c < num; c += 16) {
        float4 w[16];
#pragma unroll
        for (int j = 0; j < 16; j++) {
            int s = c + j;
            if (s < num) w[j] = W4[off[s] + tid];
            else         w[j] = make_float4(0.f, 0.f, 0.f, 0.f);
        }
        // pairwise tree to shorten the FADD chain
        float4 p0 = make_float4(0.f,0.f,0.f,0.f), p1 = p0, p2 = p0, p3 = p0;
#pragma unroll
        for (int j = 0; j < 16; j += 4) {
            p0.x += w[j+0].x; p0.y += w[j+0].y; p0.z += w[j+0].z; p0.w += w[j+0].w;
            p1.x += w[j+1].x; p1.y += w[j+1].y; p1.z += w[j+1].z; p1.w += w[j+1].w;
            p2.x += w[j+2].x; p2.y += w[j+2].y; p2.z += w[j+2].z; p2.w += w[j+2].w;
            p3.x += w[j+3].x; p3.y += w[j+3].y; p3.z += w[j+3].z; p3.w += w[j+3].w;
        }
        acc.x += (p0.x + p1.x) + (p2.x + p3.x);
        acc.y += (p0.y + p1.y) + (p2.y + p3.y);
        acc.z += (p0.z + p1.z) + (p2.z + p3.z);
        acc.w += (p0.w + p1.w) + (p2.w + p3.w);
    }
    return acc;
}

// ---------------------------------------------------------------------------
// Persistent LIF kernel: one CTA per batch element, loops over all SEQ steps.
// Thread t owns neurons {4t..4t+3} of BOTH layers (float4 state in registers).
// ---------------------------------------------------------------------------
__global__ __launch_bounds__(NT, 1)
void lif_persistent(const float* __restrict__ decay1, const float* __restrict__ decay2,
                    const float* __restrict__ th1,    const float* __restrict__ th2,
                    const float* __restrict__ v1init, const float* __restrict__ v2init,
                    const int*   __restrict__ spk_ids, const int* __restrict__ spk_num,
                    float* __restrict__ out)
{
    const int b    = blockIdx.x;
    const int tid  = threadIdx.x;
    const int lane = tid & 31;
    const int warp = tid >> 5;

    // Output sections (reference tuple order, all fp32)
    float* out_ids1 = out;
    float* out_ids2 = out + (size_t)SEQ * BATCH * SIN;
    float* out_cnt1 = out + (size_t)2 * SEQ * BATCH * SIN;
    float* out_cnt2 = out_cnt1 + (size_t)SEQ * BATCH * 2;
    float* out_st1  = out_cnt2 + (size_t)SEQ * BATCH * 2;
    float* out_st2  = out_st1  + (size_t)SEQ * BATCH * NN;

    float4 v1 = ((const float4*)v1init)[b * ROWF4 + tid];
    float4 v2 = ((const float4*)v2init)[b * ROWF4 + tid];
    const float4 d1 = ((const float4*)decay1)[tid];
    const float4 d2 = ((const float4*)decay2)[tid];
    const float4 t1 = ((const float4*)th1)[tid];
    const float4 t2 = ((const float4*)th2)[tid];
    const float4 od1 = make_float4(1.f - d1.x, 1.f - d1.y, 1.f - d1.z, 1.f - d1.w);
    const float4 od2 = make_float4(1.f - d2.x, 1.f - d2.y, 1.f - d2.z, 1.f - d2.w);
    const float4 h1 = make_float4(0.9f*t1.x, 0.9f*t1.y, 0.9f*t1.z, 0.9f*t1.w);
    const float4 h2 = make_float4(0.9f*t2.x, 0.9f*t2.y, 0.9f*t2.z, 0.9f*t2.w);

    __shared__ int s_ids[SIN];     // pre-scaled float4 row offsets (id * ROWF4)
    __shared__ int s_num;
    __shared__ int s_spk[NN];      // layer-1 spiking ids (ascending)
    __shared__ int s_spkoff[NN];   // same, pre-scaled for W2 gather
    __shared__ int s_ns[SIN];      // layer-1 non-spiking padding ids
    __shared__ int s_spk2[SIN];
    __shared__ int s_ns2[SIN];
    __shared__ int s_wsum[NWARP];
    __shared__ int s_tot;

    const float4* __restrict__ W1 = (const float4*)g_W1T;
    const float4* __restrict__ W2 = (const float4*)g_W2T;

    for (int t = 0; t < SEQ; t++) {
        // ---- stage input spikes ----
        if (tid < SIN) s_ids[tid] = spk_ids[((size_t)t * BATCH + b) * SIN + tid] * ROWF4;
        if (tid == 0)  s_num = spk_num[t * BATCH + b];
        __syncthreads();

        // ---- layer 1: sparse gather-accumulate ----
        const int num = s_num;
        float4 acc = gather_rows4(W1, s_ids, num, tid);

        v1.x = d1.x * v1.x + od1.x * acc.x;
        v1.y = d1.y * v1.y + od1.y * acc.y;
        v1.z = d1.z * v1.z + od1.z * acc.z;
        v1.w = d1.w * v1.w + od1.w * acc.w;
        const bool p0 = v1.x > t1.x, p1 = v1.y > t1.y,
                   p2 = v1.z > t1.z, p3 = v1.w > t1.w;
        int c  = (int)p0 + (int)p1 + (int)p2 + (int)p3;
        int c2 = (int)(v1.x > h1.x) + (int)(v1.y > h1.y)
               + (int)(v1.z > h1.z) + (int)(v1.w > h1.w);

        // ---- packed scan: low16 = spike count, high16 = second count ----
        int packed = c | (c2 << 16);
        int incl = packed;
#pragma unroll
        for (int o = 1; o < 32; o <<= 1) {
            int y = __shfl_up_sync(0xffffffffu, incl, o);
            if (lane >= o) incl += y;
        }
        if (lane == 31) s_wsum[warp] = incl;
        __syncthreads();
        if (warp == 0) {
            int v = (lane < NWARP) ? s_wsum[lane] : 0;
            int e = v;
#pragma unroll
            for (int o = 1; o < NWARP; o <<= 1) {
                int y = __shfl_up_sync(0xffffffffu, e, o);
                if (lane >= o) e += y;
            }
            if (lane < NWARP) s_wsum[lane] = e - v;   // exclusive
            if (lane == NWARP - 1) s_tot = e;
        }
        __syncthreads();
        int gp          = (s_wsum[warp] + (incl - packed)) & 0xffff;
        const int tot   = s_tot;
        const int c1tot = tot & 0xffff;
        const int c2tot = tot >> 16;

        // ---- emit compacted lists, reset, write state trace ----
        const int n0 = tid * 4;
        const bool pr[4] = {p0, p1, p2, p3};
#pragma unroll
        for (int k = 0; k < 4; k++) {
            int id = n0 + k;
            if (pr[k]) { s_spk[gp] = id; s_spkoff[gp] = id * ROWF4; gp++; }
            else       { int np = id - gp; if (np < SIN) s_ns[np] = id; }
        }
        if (p0) v1.x = 0.0f;
        if (p1) v1.y = 0.0f;
        if (p2) v1.z = 0.0f;
        if (p3) v1.w = 0.0f;
        __stcs(&((float4*)out_st1)[((size_t)t * BATCH + b) * ROWF4 + tid], v1);
        __syncthreads();

        if (tid < SIN) {
            int id = (tid < c1tot) ? s_spk[tid] : s_ns[tid - c1tot];
            out_ids1[((size_t)t * BATCH + b) * SIN + tid] = (float)id;
        }
        if (tid < 2)
            out_cnt1[((size_t)t * BATCH + b) * 2 + tid] = (float)(tid == 0 ? c1tot : c2tot);

        // ---- layer 2: gather W2T rows of spiking layer-1 neurons ----
        float4 acc2 = gather_rows4(W2, s_spkoff, c1tot, tid);

        v2.x = d2.x * v2.x + od2.x * acc2.x;
        v2.y = d2.y * v2.y + od2.y * acc2.y;
        v2.z = d2.z * v2.z + od2.z * acc2.z;
        v2.w = d2.w * v2.w + od2.w * acc2.w;
        const bool q0 = v2.x > t2.x, q1 = v2.y > t2.y,
                   q2 = v2.z > t2.z, q3 = v2.w > t2.w;
        c  = (int)q0 + (int)q1 + (int)q2 + (int)q3;
        c2 = (int)(v2.x > h2.x) + (int)(v2.y > h2.y)
           + (int)(v2.z > h2.z) + (int)(v2.w > h2.w);

        packed = c | (c2 << 16);
        incl = packed;
#pragma unroll
        for (int o = 1; o < 32; o <<= 1) {
            int y = __shfl_up_sync(0xffffffffu, incl, o);
            if (lane >= o) incl += y;
        }
        if (lane == 31) s_wsum[warp] = incl;
        __syncthreads();
        if (warp == 0) {
            int v = (lane < NWARP) ? s_wsum[lane] : 0;
            int e = v;
#pragma unroll
            for (int o = 1; o < NWARP; o <<= 1) {
                int y = __shfl_up_sync(0xffffffffu, e, o);
                if (lane >= o) e += y;
            }
            if (lane < NWARP) s_wsum[lane] = e - v;
            if (lane == NWARP - 1) s_tot = e;
        }
        __syncthreads();
        int gq           = (s_wsum[warp] + (incl - packed)) & 0xffff;
        const int tot2   = s_tot;
        const int c1tot2 = tot2 & 0xffff;
        const int c2tot2 = tot2 >> 16;

        const bool qr[4] = {q0, q1, q2, q3};
#pragma unroll
        for (int k = 0; k < 4; k++) {
            int id = n0 + k;
            if (qr[k]) { if (gq < SIN) s_spk2[gq] = id; gq++; }
            else       { int np = id - gq; if (np < SIN) s_ns2[np] = id; }
        }
        if (q0) v2.x = 0.0f;
        if (q1) v2.y = 0.0f;
        if (q2) v2.z = 0.0f;
        if (q3) v2.w = 0.0f;
        __stcs(&((float4*)out_st2)[((size_t)t * BATCH + b) * ROWF4 + tid], v2);
        __syncthreads();

        if (tid < SIN) {
            int id = (tid < c1tot2) ? s_spk2[tid] : s_ns2[tid - c1tot2];
            out_ids2[((size_t)t * BATCH + b) * SIN + tid] = (float)id;
        }
        if (tid < 2)
            out_cnt2[((size_t)t * BATCH + b) * 2 + tid] = (float)(tid == 0 ? c1tot2 : c2tot2);
    }
}

// ---------------------------------------------------------------------------
extern "C" void kernel_launch(void* const* d_in, const int* in_sizes, int n_in,
                              void* d_out, int out_size) {
    const float* W1     = (const float*)d_in[0];
    const float* W2     = (const float*)d_in[1];
    const float* decay1 = (const float*)d_in[2];
    const float* decay2 = (const float*)d_in[3];
    const float* th1    = (const float*)d_in[4];
    const float* th2    = (const float*)d_in[5];
    const float* v1init = (const float*)d_in[6];
    const float* v2init = (const float*)d_in[7];
    const int*   spkids = (const int*)d_in[8];
    const int*   spknum = (const int*)d_in[9];
    float* out = (float*)d_out;

    dim3 tb(32, 8), tg(32, 32, 2);
    transpose_both<<<tg, tb>>>(W1, W2);
    lif_persistent<<<BATCH, NT>>>(decay1, decay2, th1, th2,
                                  v1init, v2init, spkids, spknum, out);
}